// round 14
// baseline (speedup 1.0000x reference)
#include <cuda_runtime.h>
#include <cuda_bf16.h>
#include <math.h>

// ---------------- Model constants ----------------
#define DEPTH   24
#define DM      192       // d_model
#define DI      384       // d_inner
#define DSTATE  16
#define DTRANK  12
#define DCONV   4
#define LSEQ    401       // NP+1
#define NB      4         // batch
#define MTOK    (NB*LSEQ) // 1604
#define DXP     (DTRANK + 2*DSTATE) // 44
#define CT      24        // scan chunk length

// ---------------- Scratch (device globals; no allocation) ----------------
__device__ float g_resA    [MTOK*DM];
__device__ float g_resB    [MTOK*DM];
__device__ float g_hidden  [MTOK*DM];
__device__ float g_xz      [MTOK*2*DI];       // [:,0:384]=xx, [:,384:768]=z
__device__ float g_xconv   [2*MTOK*DI];       // per dir, silu(conv(x))
__device__ float g_dbl     [2*MTOK*DXP];      // xproj out [dt_r(12), B(16), C(16)]
__device__ float g_dt      [2*MTOK*DI];       // softplus(dt)
__device__ float g_y       [2*MTOK*DI];       // gated outputs per dir

// ---------------- Patch embed + cls + pos ----------------
__global__ void k_patch(const float* __restrict__ x, const float* __restrict__ pe_w,
                        const float* __restrict__ pe_b, const float* __restrict__ cls,
                        const float* __restrict__ pos)
{
    int p = blockIdx.x;          // 0..399
    int b = blockIdx.y;          // 0..3
    int tid = threadIdx.x;       // 256
    __shared__ float sp[256];
    int ph = p / 200, pw = p % 200;
    int i = tid >> 4, j = tid & 15;
    sp[tid] = x[b*32*3200 + (ph*16 + i)*3200 + pw*16 + j];
    __syncthreads();
    if (tid < DM) {
        int c = tid;
        const float* w = pe_w + c*256;
        float acc = pe_b[c];
        #pragma unroll 8
        for (int k = 0; k < 256; k++) acc += sp[k]*w[k];
        int t = p + 1;
        float v = acc + pos[t*DM + c];
        int m = b*LSEQ + t;
        g_hidden[m*DM + c] = v;
        g_resA[m*DM + c] = v;
        if (p == 0) {
            float cv = cls[c] + pos[c];
            int m0 = b*LSEQ;
            g_hidden[m0*DM + c] = cv;
            g_resA[m0*DM + c] = cv;
        }
    }
}

// ---------------- GEMM0 + fused prenorm ----------------
// res_out = res_in + hidden (written by by==0 blocks); A = rmsnorm(res_out)*norm_w
// C = g_xz[1604,768] = A[1604,192] @ W[768,192]^T ; 128x64 tiles
__global__ void k_gemm0n(const float* __restrict__ W, const float* __restrict__ norm_w,
                         int parity)
{
    const float* res_in  = parity ? g_resB : g_resA;
    float*       res_out = parity ? g_resA : g_resB;

    __shared__ float As[2][16][132];
    __shared__ float Ws[2][16][68];
    __shared__ float rscale[128];
    __shared__ float snw[DM];

    int tid = threadIdx.x;
    int warp = tid >> 5, lane = tid & 31;
    int m0 = blockIdx.x*128, n0 = blockIdx.y*64;
    bool wr_res = (blockIdx.y == 0);

    if (tid < DM) snw[tid] = norm_w[tid];

    // prenorm phase: 8 warps x 16 rows
    for (int rr = 0; rr < 16; rr++) {
        int row = warp*16 + rr;
        int m = m0 + row;
        if (m < MTOK) {
            float ss = 0.f;
            float vv[6];
            #pragma unroll
            for (int u = 0; u < 6; u++) {
                int c = lane + u*32;
                float v = res_in[(size_t)m*DM + c] + g_hidden[(size_t)m*DM + c];
                vv[u] = v; ss += v*v;
            }
            if (wr_res) {
                #pragma unroll
                for (int u = 0; u < 6; u++)
                    res_out[(size_t)m*DM + lane + u*32] = vv[u];
            }
            #pragma unroll
            for (int o = 16; o; o >>= 1) ss += __shfl_xor_sync(~0u, ss, o);
            if (lane == 0) rscale[row] = rsqrtf(ss*(1.f/DM) + 1e-5f);
        }
    }
    __syncthreads();

    int arow = tid >> 1, akq = tid & 1;
    int wrow = tid >> 2, wkq = tid & 3;
    int tx = tid & 15, ty = tid >> 4;
    float4 pa0, pa1, pw;

    auto ldA = [&](int k0) {
        int m = m0 + arow;
        if (m < MTOK) {
            pa0 = *(const float4*)(res_in + (size_t)m*DM + k0 + akq*8);
            pa1 = *(const float4*)(res_in + (size_t)m*DM + k0 + akq*8 + 4);
            float4 h0 = *(const float4*)(g_hidden + (size_t)m*DM + k0 + akq*8);
            float4 h1 = *(const float4*)(g_hidden + (size_t)m*DM + k0 + akq*8 + 4);
            float rs = rscale[arow];
            int kb = k0 + akq*8;
            pa0.x = (pa0.x+h0.x)*rs*snw[kb+0]; pa0.y = (pa0.y+h0.y)*rs*snw[kb+1];
            pa0.z = (pa0.z+h0.z)*rs*snw[kb+2]; pa0.w = (pa0.w+h0.w)*rs*snw[kb+3];
            pa1.x = (pa1.x+h1.x)*rs*snw[kb+4]; pa1.y = (pa1.y+h1.y)*rs*snw[kb+5];
            pa1.z = (pa1.z+h1.z)*rs*snw[kb+6]; pa1.w = (pa1.w+h1.w)*rs*snw[kb+7];
        } else { pa0 = make_float4(0,0,0,0); pa1 = pa0; }
    };
    auto stA = [&](int buf) {
        As[buf][akq*8+0][arow]=pa0.x; As[buf][akq*8+1][arow]=pa0.y;
        As[buf][akq*8+2][arow]=pa0.z; As[buf][akq*8+3][arow]=pa0.w;
        As[buf][akq*8+4][arow]=pa1.x; As[buf][akq*8+5][arow]=pa1.y;
        As[buf][akq*8+6][arow]=pa1.z; As[buf][akq*8+7][arow]=pa1.w;
    };

    ldA(0);
    pw = *(const float4*)(W + (size_t)(n0 + wrow)*DM + wkq*4);
    stA(0);
    Ws[0][wkq*4+0][wrow]=pw.x;  Ws[0][wkq*4+1][wrow]=pw.y;
    Ws[0][wkq*4+2][wrow]=pw.z;  Ws[0][wkq*4+3][wrow]=pw.w;
    __syncthreads();

    float acc[8][4] = {};
    const int NK = DM/16;  // 12
    for (int kt = 0; kt < NK; kt++) {
        if (kt + 1 < NK) {
            ldA((kt+1)*16);
            pw = *(const float4*)(W + (size_t)(n0 + wrow)*DM + (kt+1)*16 + wkq*4);
        }
        int buf = kt & 1;
        #pragma unroll
        for (int k = 0; k < 16; k++) {
            float4 bv = *(const float4*)&Ws[buf][k][tx*4];
            float4 a0 = *(const float4*)&As[buf][k][ty*8];
            float4 a1 = *(const float4*)&As[buf][k][ty*8+4];
            float av[8] = {a0.x,a0.y,a0.z,a0.w,a1.x,a1.y,a1.z,a1.w};
            float bw[4] = {bv.x,bv.y,bv.z,bv.w};
            #pragma unroll
            for (int i2 = 0; i2 < 8; i2++)
                #pragma unroll
                for (int j2 = 0; j2 < 4; j2++)
                    acc[i2][j2] = fmaf(av[i2], bw[j2], acc[i2][j2]);
        }
        if (kt + 1 < NK) {
            int bn = buf ^ 1;
            stA(bn);
            Ws[bn][wkq*4+0][wrow]=pw.x;  Ws[bn][wkq*4+1][wrow]=pw.y;
            Ws[bn][wkq*4+2][wrow]=pw.z;  Ws[bn][wkq*4+3][wrow]=pw.w;
        }
        __syncthreads();
    }
    #pragma unroll
    for (int i2 = 0; i2 < 8; i2++) {
        int m = m0 + ty*8 + i2;
        if (m < MTOK) {
            float4 v = make_float4(acc[i2][0], acc[i2][1], acc[i2][2], acc[i2][3]);
            *(float4*)(g_xz + (size_t)m*2*DI + n0 + tx*4) = v;
        }
    }
}

// ---------------- conv+silu + xproj GEMM + dt projection (16-row tiles) ----------------
// Phase1 (parallel): As[ch][m] = silu(conv(g_xz)), also -> g_xconv
// Phase2: C = g_dbl[16,44] = A @ W^T (A from smem)
// Phase3 (parallel): g_dt = softplus(C[:,0:12] @ dtw^T + dtb)
__global__ void k_xp(const float* __restrict__ W, const float* __restrict__ cw,
                     const float* __restrict__ cb, const float* __restrict__ dtw,
                     const float* __restrict__ dtb)
{
    __shared__ float As[DI][17];   // [ch][m], 16 rows padded to 17
    __shared__ float Ws[32][52];
    __shared__ float sdbl[16][12];
    int tid = threadIdx.x;         // 256
    int m0 = blockIdx.x*16;

    // ---- Phase 1: conv + silu ----
    #pragma unroll 4
    for (int p = 0; p < 24; p++) {
        int idx = p*256 + tid;         // 0..6143
        int ml = idx / DI;
        int ch = idx - ml*DI;
        int m = m0 + ml;
        float v = 0.f;
        if (m < 2*MTOK) {
            int dirm = (m >= MTOK) ? 1 : 0;
            int rr = m - dirm*MTOK;
            int bb = rr / LSEQ, t = rr - bb*LSEQ;
            int rb = bb*LSEQ;
            float a = cb[ch];
            #pragma unroll
            for (int tp = 0; tp < 4; tp++) {
                int tt = dirm ? (t + 3 - tp) : (t - 3 + tp);
                if (tt >= 0 && tt < LSEQ)
                    a = fmaf(g_xz[(size_t)(rb + tt)*2*DI + ch], cw[ch*4 + tp], a);
            }
            v = a / (1.f + __expf(-a));
            g_xconv[(size_t)m*DI + ch] = v;
        }
        As[ch][ml] = v;
    }
    __syncthreads();

    // ---- Phase 2: GEMM 16x44 over K=384 ----
    int ty = tid / 11, tx = tid - ty*11;   // active: ty<16
    bool act = (ty < 16);
    float acc[4] = {0.f, 0.f, 0.f, 0.f};
    for (int k0 = 0; k0 < DI; k0 += 32) {
        for (int i = tid; i < 384; i += 256) {
            int nr = i >> 3, kq = i & 7;
            float4 v = make_float4(0,0,0,0);
            if (nr < DXP) v = *(const float4*)(W + (size_t)nr*DI + k0 + kq*4);
            Ws[kq*4+0][nr]=v.x; Ws[kq*4+1][nr]=v.y; Ws[kq*4+2][nr]=v.z; Ws[kq*4+3][nr]=v.w;
        }
        __syncthreads();
        if (act) {
            #pragma unroll
            for (int k = 0; k < 32; k++) {
                float a = As[k0 + k][ty];
                float4 w4 = *(const float4*)&Ws[k][tx*4];
                acc[0] = fmaf(a, w4.x, acc[0]);
                acc[1] = fmaf(a, w4.y, acc[1]);
                acc[2] = fmaf(a, w4.z, acc[2]);
                acc[3] = fmaf(a, w4.w, acc[3]);
            }
        }
        __syncthreads();
    }
    if (act) {
        int m = m0 + ty;
        if (m < 2*MTOK) {
            float4 v = make_float4(acc[0], acc[1], acc[2], acc[3]);
            *(float4*)(g_dbl + (size_t)m*DXP + tx*4) = v;
        }
        if (tx < 3) {
            #pragma unroll
            for (int j = 0; j < 4; j++) sdbl[ty][tx*4 + j] = acc[j];
        }
    }
    __syncthreads();

    // ---- Phase 3: dt projection ----
    #pragma unroll 4
    for (int p = 0; p < 24; p++) {
        int idx = p*256 + tid;
        int ml = idx / DI;
        int ch = idx - ml*DI;
        int m = m0 + ml;
        if (m < 2*MTOK) {
            float s = dtb[ch];
            const float* wr = dtw + ch*DTRANK;
            #pragma unroll
            for (int r = 0; r < DTRANK; r++) s = fmaf(sdbl[ml][r], wr[r], s);
            g_dt[(size_t)m*DI + ch] = (s > 20.f) ? s : log1pf(__expf(s));
        }
    }
}

// ---------------- selective scan: smem partials, no shfl chain ----------------
__global__ void k_scan(const float* __restrict__ Alog_f, const float* __restrict__ Alog_b,
                       const float* __restrict__ Dp)
{
    int cblk = blockIdx.x;  // 0..23
    int b = blockIdx.y;
    int dir = blockIdx.z;
    int tid = threadIdx.x;  // 256
    int warp = tid >> 5, lane = tid & 31;
    int dloc = warp*2 + (lane >> 4);
    int n = lane & 15;
    int d = cblk*16 + dloc;

    __shared__ float sbuf[2][5][CT*16];   // 0=dt 1=xv 2=B 3=C 4=z
    __shared__ float sp[CT][16][20];
    __shared__ float s_Dk[16];
    if (tid < 16) s_Dk[tid] = Dp[cblk*16 + tid];

    const float* Alog = dir ? Alog_b : Alog_f;
    float A = -__expf(Alog[d*DSTATE + n]);
    int rowbase = b*LSEQ;
    int gbase = dir*MTOK + rowbase;

    auto stage = [&](int t0, int bf) {
        if (tid < 96) {
            int tt = t0 + (tid >> 2);
            if (tt < LSEQ) {
                int mm = dir ? (LSEQ-1 - tt) : tt;
                int gi = gbase + mm;
                int jq = (tid & 3)*4;
                int idx = (tt - t0)*16 + jq;
                *(float4*)&sbuf[bf][0][idx] = *(const float4*)(g_dt    + (size_t)gi*DI + cblk*16 + jq);
                *(float4*)&sbuf[bf][1][idx] = *(const float4*)(g_xconv + (size_t)gi*DI + cblk*16 + jq);
                *(float4*)&sbuf[bf][2][idx] = *(const float4*)(g_dbl   + (size_t)gi*DXP + DTRANK + jq);
                *(float4*)&sbuf[bf][3][idx] = *(const float4*)(g_dbl   + (size_t)gi*DXP + DTRANK + DSTATE + jq);
                *(float4*)&sbuf[bf][4][idx] = *(const float4*)(g_xz    + (size_t)(rowbase+mm)*2*DI + DI + cblk*16 + jq);
            }
        }
    };

    stage(0, 0);
    __syncthreads();

    float h = 0.f;
    const int nch = (LSEQ + CT - 1)/CT;   // 17
    for (int c = 0; c < nch; c++) {
        int bf = c & 1;
        int tmax = min(CT, LSEQ - c*CT);
        #pragma unroll 4
        for (int k = 0; k < tmax; k++) {
            float dt = sbuf[bf][0][k*16 + dloc];
            float xv = sbuf[bf][1][k*16 + dloc];
            float Bn = sbuf[bf][2][k*16 + n];
            float Cn = sbuf[bf][3][k*16 + n];
            h = fmaf(__expf(dt*A), h, dt*xv*Bn);
            sp[k][dloc][n] = h*Cn;
        }
        __syncthreads();
        if (c + 1 < nch) stage((c+1)*CT, bf ^ 1);
        for (int o = tid; o < tmax*16; o += 256) {
            int k = o >> 4, dd = o & 15;
            float4 p0 = *(const float4*)&sp[k][dd][0];
            float4 p1 = *(const float4*)&sp[k][dd][4];
            float4 p2 = *(const float4*)&sp[k][dd][8];
            float4 p3 = *(const float4*)&sp[k][dd][12];
            float s = ((p0.x+p0.y)+(p0.z+p0.w)) + ((p1.x+p1.y)+(p1.z+p1.w))
                    + ((p2.x+p2.y)+(p2.z+p2.w)) + ((p3.x+p3.y)+(p3.z+p3.w));
            float xvv = sbuf[bf][1][k*16 + dd];
            float z   = sbuf[bf][4][k*16 + dd];
            float y = fmaf(xvv, s_Dk[dd], s);
            int tglob = c*CT + k;
            int mm = dir ? (LSEQ-1 - tglob) : tglob;
            g_y[(size_t)(gbase + mm)*DI + cblk*16 + dd] = y * (z / (1.f + __expf(-z)));
        }
        __syncthreads();
    }
}

// ---------------- GEMM1: g_hidden[1604,192] = (y0+y1)[1604,384] @ W[192,384]^T ----------------
__global__ void k_gemm1(const float* __restrict__ W)
{
    __shared__ float As[2][32][68];
    __shared__ float Ws[2][32][68];
    int tid = threadIdx.x;
    int m0 = blockIdx.x*64, n0 = blockIdx.y*64;
    int row = tid >> 2, kq0 = (tid & 3)*2;
    int tx = tid & 15, ty = tid >> 4;
    float4 pa0, pa1, pw0, pw1;

    {
        int m = m0 + row;
        if (m < MTOK) {
            float4 a = *(const float4*)(g_y + m*DI + kq0*4);
            float4 b = *(const float4*)(g_y + (size_t)MTOK*DI + m*DI + kq0*4);
            pa0 = make_float4(a.x+b.x, a.y+b.y, a.z+b.z, a.w+b.w);
            a = *(const float4*)(g_y + m*DI + kq0*4 + 4);
            b = *(const float4*)(g_y + (size_t)MTOK*DI + m*DI + kq0*4 + 4);
            pa1 = make_float4(a.x+b.x, a.y+b.y, a.z+b.z, a.w+b.w);
        } else { pa0 = make_float4(0,0,0,0); pa1 = pa0; }
        pw0 = *(const float4*)(W + (n0 + row)*DI + kq0*4);
        pw1 = *(const float4*)(W + (n0 + row)*DI + kq0*4 + 4);
        As[0][kq0*4+0][row]=pa0.x; As[0][kq0*4+1][row]=pa0.y;
        As[0][kq0*4+2][row]=pa0.z; As[0][kq0*4+3][row]=pa0.w;
        As[0][kq0*4+4][row]=pa1.x; As[0][kq0*4+5][row]=pa1.y;
        As[0][kq0*4+6][row]=pa1.z; As[0][kq0*4+7][row]=pa1.w;
        Ws[0][kq0*4+0][row]=pw0.x; Ws[0][kq0*4+1][row]=pw0.y;
        Ws[0][kq0*4+2][row]=pw0.z; Ws[0][kq0*4+3][row]=pw0.w;
        Ws[0][kq0*4+4][row]=pw1.x; Ws[0][kq0*4+5][row]=pw1.y;
        Ws[0][kq0*4+6][row]=pw1.z; Ws[0][kq0*4+7][row]=pw1.w;
    }
    __syncthreads();

    float acc[4][4] = {};
    const int NK = DI/32;  // 12
    for (int kt = 0; kt < NK; kt++) {
        if (kt + 1 < NK) {
            int k0 = (kt+1)*32;
            int m = m0 + row;
            if (m < MTOK) {
                float4 a = *(const float4*)(g_y + m*DI + k0 + kq0*4);
                float4 b = *(const float4*)(g_y + (size_t)MTOK*DI + m*DI + k0 + kq0*4);
                pa0 = make_float4(a.x+b.x, a.y+b.y, a.z+b.z, a.w+b.w);
                a = *(const float4*)(g_y + m*DI + k0 + kq0*4 + 4);
                b = *(const float4*)(g_y + (size_t)MTOK*DI + m*DI + k0 + kq0*4 + 4);
                pa1 = make_float4(a.x+b.x, a.y+b.y, a.z+b.z, a.w+b.w);
            } else { pa0 = make_float4(0,0,0,0); pa1 = pa0; }
            pw0 = *(const float4*)(W + (n0 + row)*DI + k0 + kq0*4);
            pw1 = *(const float4*)(W + (n0 + row)*DI + k0 + kq0*4 + 4);
        }
        int buf = kt & 1;
        #pragma unroll
        for (int k = 0; k < 32; k++) {
            float4 bv = *(const float4*)&Ws[buf][k][tx*4];
            float4 a0 = *(const float4*)&As[buf][k][ty*4];
            float av[4] = {a0.x,a0.y,a0.z,a0.w};
            float bw[4] = {bv.x,bv.y,bv.z,bv.w};
            #pragma unroll
            for (int i2 = 0; i2 < 4; i2++)
                #pragma unroll
                for (int j2 = 0; j2 < 4; j2++)
                    acc[i2][j2] = fmaf(av[i2], bw[j2], acc[i2][j2]);
        }
        if (kt + 1 < NK) {
            int bn = buf ^ 1;
            As[bn][kq0*4+0][row]=pa0.x; As[bn][kq0*4+1][row]=pa0.y;
            As[bn][kq0*4+2][row]=pa0.z; As[bn][kq0*4+3][row]=pa0.w;
            As[bn][kq0*4+4][row]=pa1.x; As[bn][kq0*4+5][row]=pa1.y;
            As[bn][kq0*4+6][row]=pa1.z; As[bn][kq0*4+7][row]=pa1.w;
            Ws[bn][kq0*4+0][row]=pw0.x; Ws[bn][kq0*4+1][row]=pw0.y;
            Ws[bn][kq0*4+2][row]=pw0.z; Ws[bn][kq0*4+3][row]=pw0.w;
            Ws[bn][kq0*4+4][row]=pw1.x; Ws[bn][kq0*4+5][row]=pw1.y;
            Ws[bn][kq0*4+6][row]=pw1.z; Ws[bn][kq0*4+7][row]=pw1.w;
        }
        __syncthreads();
    }
    #pragma unroll
    for (int i2 = 0; i2 < 4; i2++) {
        int m = m0 + ty*4 + i2;
        if (m < MTOK) {
            float4 v = make_float4(acc[i2][0], acc[i2][1], acc[i2][2], acc[i2][3]);
            *(float4*)(g_hidden + m*DM + n0 + tx*4) = v;
        }
    }
}

// ---------------- final norm + head (cls token only; residual = g_resA after 24 layers) ----------------
__global__ void k_head(const float* __restrict__ nfw, const float* __restrict__ hw,
                       const float* __restrict__ hb, float* __restrict__ out)
{
    int b = blockIdx.x;
    int tid = threadIdx.x; // 192
    __shared__ float rn[DM];
    __shared__ float red[6];
    int m = b*LSEQ;
    float v = g_resA[m*DM + tid] + g_hidden[m*DM + tid];
    float ss = v*v;
    #pragma unroll
    for (int o = 16; o; o >>= 1) ss += __shfl_xor_sync(~0u, ss, o);
    if ((tid & 31) == 0) red[tid >> 5] = ss;
    __syncthreads();
    float tot = red[0] + red[1] + red[2] + red[3] + red[4] + red[5];
    float rstd = rsqrtf(tot*(1.f/DM) + 1e-5f);
    rn[tid] = v*rstd*nfw[tid];
    __syncthreads();
    if (tid < 22) {
        float s = hb[tid];
        const float* wr = hw + tid*DM;
        #pragma unroll 4
        for (int k = 0; k < DM; k++) s = fmaf(rn[k], wr[k], s);
        out[b*22 + tid] = s;
    }
}

// ---------------- launcher ----------------
extern "C" void kernel_launch(void* const* d_in, const int* in_sizes, int n_in,
                              void* d_out, int out_size)
{
    const float* x         = (const float*)d_in[0];
    const float* pe_w      = (const float*)d_in[1];
    const float* pe_b      = (const float*)d_in[2];
    const float* cls_token = (const float*)d_in[3];
    const float* pos_embed = (const float*)d_in[4];
    const float* norm_w    = (const float*)d_in[5];
    const float* in_proj_w = (const float*)d_in[6];
    const float* cw        = (const float*)d_in[7];
    const float* cb        = (const float*)d_in[8];
    const float* xproj_w   = (const float*)d_in[9];
    const float* dtproj_w  = (const float*)d_in[10];
    const float* dtproj_b  = (const float*)d_in[11];
    const float* A_log     = (const float*)d_in[12];
    const float* A_b_log   = (const float*)d_in[13];
    const float* Dp        = (const float*)d_in[14];
    const float* outproj_w = (const float*)d_in[15];
    const float* norm_f_w  = (const float*)d_in[16];
    const float* head_w    = (const float*)d_in[17];
    const float* head_b    = (const float*)d_in[18];
    float* out = (float*)d_out;

    k_patch<<<dim3(400, NB), 256>>>(x, pe_w, pe_b, cls_token, pos_embed);

    for (int l = 0; l < DEPTH; l++) {
        k_gemm0n<<<dim3((MTOK + 127)/128, (2*DI)/64), 256>>>(in_proj_w + (size_t)l*2*DI*DM,
                                                             norm_w + l*DM, l & 1);
        k_xp<<<(2*MTOK + 15)/16, 256>>>(xproj_w + (size_t)l*DXP*DI,
                                        cw + l*DI*DCONV, cb + l*DI,
                                        dtproj_w + (size_t)l*DI*DTRANK, dtproj_b + l*DI);
        k_scan<<<dim3(DI/16, NB, 2), 256>>>(A_log + (size_t)l*DI*DSTATE,
                                            A_b_log + (size_t)l*DI*DSTATE,
                                            Dp + l*DI);
        k_gemm1<<<dim3((MTOK + 63)/64, DM/64), 256>>>(outproj_w + (size_t)l*DM*DI);
    }

    k_head<<<NB, DM>>>(norm_f_w, head_w, head_b, out);
}